// round 7
// baseline (speedup 1.0000x reference)
#include <cuda_runtime.h>
#include <stdint.h>

#define NUM_FIELDS 10
#define VOCAB      100000
#define EMBED      16            // floats per embedding row (64 bytes)
#define BATCH      16384
#define NPAIRS     45            // C(10,2)
#define B_PER_BLK  64            // quads per 256-thread block
#define NPGRP      23            // ceil(45/2) pair-groups

// triu_indices(10, k=1): pair p -> (ii[p], jj[p]) with ii < jj
__constant__ unsigned char c_ii[NPAIRS] = {
    0,0,0,0,0,0,0,0,0,
    1,1,1,1,1,1,1,1,
    2,2,2,2,2,2,2,
    3,3,3,3,3,3,
    4,4,4,4,4,
    5,5,5,5,
    6,6,6,
    7,7,
    8
};
__constant__ unsigned char c_jj[NPAIRS] = {
    1,2,3,4,5,6,7,8,9,
    2,3,4,5,6,7,8,9,
    3,4,5,6,7,8,9,
    4,5,6,7,8,9,
    5,6,7,8,9,
    6,7,8,9,
    7,8,9,
    8,9,
    9
};

// PAIR-MAJOR grid (R6 win), now 2 pairs per quad-thread:
//   blockIdx.y = pair-group (pairs 2y, 2y+1), blockIdx.x = 64-wide b tile.
//   -> 4 independent 16B gathers per thread (2x MLP), 128B contiguous
//      output span per quad, ~3 broadcast index loads per thread.
// Concurrent live gather footprint stays ~10 pair slots (~128MB) -> the
// DRAM-row/TLB locality from R6 is preserved.
__global__ __launch_bounds__(256)
void ffm_kernel(const int*    __restrict__ x,      // int32 (16384, 10)
                const float4* __restrict__ emb,    // (10, 1e6, 16) as float4[40M]
                float4*       __restrict__ out)    // (16384, 45, 16) as float4
{
    int q    = threadIdx.x & 3;
    int quad = threadIdx.x >> 2;                   // 0..63
    int b    = blockIdx.x * B_PER_BLK + quad;      // exact fit: 256*64 = 16384
    int p0   = blockIdx.y * 2;                     // uniform per block
    int p1   = p0 + 1;
    bool has1 = (p1 < NPAIRS);

    int i0 = c_ii[p0], j0 = c_jj[p0];
    int i1 = has1 ? c_ii[p1] : 0;
    int j1 = has1 ? c_jj[p1] : 1;

    const int* xb = x + b * NUM_FIELDS;
    int xi0 = xb[i0], xj0 = xb[j0];
    int xi1 = xb[i1], xj1 = xb[j1];
    xi0 = min(max(xi0, 0), VOCAB - 1);
    xj0 = min(max(xj0, 0), VOCAB - 1);
    xi1 = min(max(xi1, 0), VOCAB - 1);
    xj1 = min(max(xj1, 0), VOCAB - 1);

    // out[b,p] = emb[j, x[b,i]+i*V] * emb[i, x[b,j]+j*V]
    const size_t TBL = (size_t)NUM_FIELDS * VOCAB;
    size_t rA0 = (size_t)j0 * TBL + (size_t)xi0 + (size_t)i0 * VOCAB;
    size_t rB0 = (size_t)i0 * TBL + (size_t)xj0 + (size_t)j0 * VOCAB;
    size_t rA1 = (size_t)j1 * TBL + (size_t)xi1 + (size_t)i1 * VOCAB;
    size_t rB1 = (size_t)i1 * TBL + (size_t)xj1 + (size_t)j1 * VOCAB;

    // 4 independent streaming gathers in flight (rows used exactly once)
    float4 a0 = __ldcs(emb + rA0 * (EMBED / 4) + q);
    float4 v0 = __ldcs(emb + rB0 * (EMBED / 4) + q);
    float4 a1, v1;
    if (has1) {
        a1 = __ldcs(emb + rA1 * (EMBED / 4) + q);
        v1 = __ldcs(emb + rB1 * (EMBED / 4) + q);
    }

    float4 o0;
    o0.x = a0.x * v0.x; o0.y = a0.y * v0.y;
    o0.z = a0.z * v0.z; o0.w = a0.w * v0.w;

    float4* dst = out + ((size_t)b * NPAIRS + p0) * (EMBED / 4) + q;
    __stcs(dst, o0);
    if (has1) {
        float4 o1;
        o1.x = a1.x * v1.x; o1.y = a1.y * v1.y;
        o1.z = a1.z * v1.z; o1.w = a1.w * v1.w;
        __stcs(dst + (EMBED / 4), o1);
    }
}

extern "C" void kernel_launch(void* const* d_in, const int* in_sizes, int n_in,
                              void* d_out, int out_size)
{
    const int*    x   = (const int*)d_in[0];      // indices (int32 on device)
    const float4* emb = (const float4*)d_in[1];   // float32 (10, 1e6, 16)
    float4*       out = (float4*)d_out;           // float32 (16384, 45, 16)

    dim3 grid(BATCH / B_PER_BLK, NPGRP);          // (256, 23)
    ffm_kernel<<<grid, 256>>>(x, emb, out);
}

// round 8
// speedup vs baseline: 1.0281x; 1.0281x over previous
#include <cuda_runtime.h>
#include <stdint.h>

#define NUM_FIELDS 10
#define VOCAB      100000
#define EMBED      16            // floats per embedding row (64 bytes)
#define BATCH      16384
#define NPAIRS     45            // C(10,2)
#define BLOCK      128
#define B_PER_BLK  (BLOCK / 4)   // 32 quads per block

// triu_indices(10, k=1): pair p -> (ii[p], jj[p]) with ii < jj
__constant__ unsigned char c_ii[NPAIRS] = {
    0,0,0,0,0,0,0,0,0,
    1,1,1,1,1,1,1,1,
    2,2,2,2,2,2,2,
    3,3,3,3,3,3,
    4,4,4,4,4,
    5,5,5,5,
    6,6,6,
    7,7,
    8
};
__constant__ unsigned char c_jj[NPAIRS] = {
    1,2,3,4,5,6,7,8,9,
    2,3,4,5,6,7,8,9,
    3,4,5,6,7,8,9,
    4,5,6,7,8,9,
    5,6,7,8,9,
    6,7,8,9,
    7,8,9,
    8,9,
    9
};

// PAIR-MAJOR grid (R6 win), tightened: 128-thread blocks -> 512 CTAs per
// pair slot -> the ~1184 resident CTAs span only ~2.3 pair slots (~30MB
// live gather footprint vs ~60MB in R6), maximizing DRAM-row/TLB locality.
// 4 lanes per (b,p): lane q handles float4 q of both rows (coalesced 64B).
__global__ __launch_bounds__(BLOCK)
void ffm_kernel(const int*    __restrict__ x,      // int32 (16384, 10)
                const float4* __restrict__ emb,    // (10, 1e6, 16) as float4[40M]
                float4*       __restrict__ out)    // (16384, 45, 16) as float4
{
    int q    = threadIdx.x & 3;
    int quad = threadIdx.x >> 2;                   // 0..31
    int b    = blockIdx.x * B_PER_BLK + quad;      // exact fit: 512*32 = 16384
    int p    = blockIdx.y;                         // uniform per block
    int i    = c_ii[p];
    int j    = c_jj[p];

    // broadcast within quad
    int xi = x[b * NUM_FIELDS + i];
    int xj = x[b * NUM_FIELDS + j];
    xi = min(max(xi, 0), VOCAB - 1);
    xj = min(max(xj, 0), VOCAB - 1);

    // out[b,p] = emb[j, x[b,i]+i*V] * emb[i, x[b,j]+j*V]
    size_t rowA = (size_t)j * (NUM_FIELDS * (size_t)VOCAB) + (size_t)xi + (size_t)i * VOCAB;
    size_t rowB = (size_t)i * (NUM_FIELDS * (size_t)VOCAB) + (size_t)xj + (size_t)j * VOCAB;

    // Streaming loads: rows are used exactly once.
    float4 a = __ldcs(emb + rowA * (EMBED / 4) + q);
    float4 v = __ldcs(emb + rowB * (EMBED / 4) + q);

    float4 o;
    o.x = a.x * v.x;
    o.y = a.y * v.y;
    o.z = a.z * v.z;
    o.w = a.w * v.w;

    // 64B sector-complete chunk at stride 2880B; evict-first write-back.
    __stcs(out + ((size_t)b * NPAIRS + p) * (EMBED / 4) + q, o);
}

extern "C" void kernel_launch(void* const* d_in, const int* in_sizes, int n_in,
                              void* d_out, int out_size)
{
    const int*    x   = (const int*)d_in[0];      // indices (int32 on device)
    const float4* emb = (const float4*)d_in[1];   // float32 (10, 1e6, 16)
    float4*       out = (float4*)d_out;           // float32 (16384, 45, 16)

    dim3 grid(BATCH / B_PER_BLK, NPAIRS);         // (512, 45)
    ffm_kernel<<<grid, BLOCK>>>(x, emb, out);
}